// round 4
// baseline (speedup 1.0000x reference)
#include <cuda_runtime.h>
#include <cstdint>

// IDWT (inverse Haar wavelet). Inputs LL,LH,HL,HH: [B=16,C=64,h=128,w=128] f32.
// Output: [B,C,256,256] f32. Closed-form 2x2 butterfly, s^2 = 0.5.
//
// Persistent grid-stride version: exactly one full wave of CTAs
// (148 SMs x 8 CTAs = 1184 blocks of 256 threads), each looping over
// ~14 quads. No wave transitions; memory queue stays full until the tail.

static constexpr int W4 = 32;                      // w/4
static constexpr int NROWS = 16 * 64 * 128;        // B*C*h = 131072
static constexpr int NQUADS = NROWS * W4;          // 4,194,304
static constexpr int NBLOCKS = 148 * 8;            // 1184 (one full wave @ occ 8)
static constexpr int NTHREADS = 256;
static constexpr int STRIDE = NBLOCKS * NTHREADS;  // 303,104

__global__ __launch_bounds__(NTHREADS) void idwt_haar_kernel(
    const float4* __restrict__ LL,
    const float4* __restrict__ LH,
    const float4* __restrict__ HL,
    const float4* __restrict__ HH,
    float4* __restrict__ out)
{
    int tid0 = blockIdx.x * NTHREADS + threadIdx.x;

    for (int tid = tid0; tid < NQUADS; tid += STRIDE) {
        float4 ll = __ldcs(&LL[tid]);
        float4 lh = __ldcs(&LH[tid]);
        float4 hl = __ldcs(&HL[tid]);
        float4 hh = __ldcs(&HH[tid]);

        int row = tid >> 5;        // bc*128 + i
        int jq  = tid & 31;

        int bc = row >> 7;
        int i  = row & 127;

        size_t obase = ((size_t)bc * 256 + 2 * i) * 64 + (size_t)jq * 2;

        float4 t0, t1, b0, b1;
        // butterfly via sum/diff factoring (fewer ops; compute is not the
        // bottleneck but keeps issue slots free)
        float s0 = ll.x + hh.x, d0 = ll.x - hh.x;
        float s1 = lh.x + hl.x, d1 = lh.x - hl.x;
        t0.x = 0.5f * (s0 - s1);
        t0.y = 0.5f * (d0 + d1);
        b0.x = 0.5f * (d0 - d1);
        b0.y = 0.5f * (s0 + s1);

        s0 = ll.y + hh.y; d0 = ll.y - hh.y;
        s1 = lh.y + hl.y; d1 = lh.y - hl.y;
        t0.z = 0.5f * (s0 - s1);
        t0.w = 0.5f * (d0 + d1);
        b0.z = 0.5f * (d0 - d1);
        b0.w = 0.5f * (s0 + s1);

        s0 = ll.z + hh.z; d0 = ll.z - hh.z;
        s1 = lh.z + hl.z; d1 = lh.z - hl.z;
        t1.x = 0.5f * (s0 - s1);
        t1.y = 0.5f * (d0 + d1);
        b1.x = 0.5f * (d0 - d1);
        b1.y = 0.5f * (s0 + s1);

        s0 = ll.w + hh.w; d0 = ll.w - hh.w;
        s1 = lh.w + hl.w; d1 = lh.w - hl.w;
        t1.z = 0.5f * (s0 - s1);
        t1.w = 0.5f * (d0 + d1);
        b1.z = 0.5f * (d0 - d1);
        b1.w = 0.5f * (s0 + s1);

        __stcs(&out[obase + 0], t0);
        __stcs(&out[obase + 1], t1);
        __stcs(&out[obase + 64 + 0], b0);
        __stcs(&out[obase + 64 + 1], b1);
    }
}

extern "C" void kernel_launch(void* const* d_in, const int* in_sizes, int n_in,
                              void* d_out, int out_size)
{
    const float4* LL = (const float4*)d_in[0];
    const float4* LH = (const float4*)d_in[1];
    const float4* HL = (const float4*)d_in[2];
    const float4* HH = (const float4*)d_in[3];

    float4* out = (float4*)d_out;

    idwt_haar_kernel<<<NBLOCKS, NTHREADS>>>(LL, LH, HL, HH, out);
}

// round 5
// speedup vs baseline: 1.1182x; 1.1182x over previous
#include <cuda_runtime.h>
#include <cstdint>

// IDWT (inverse Haar wavelet). Inputs LL,LH,HL,HH: [B=16,C=64,h=128,w=128] f32.
// Output: [B,C,256,256] f32. Closed-form 2x2 butterfly, s^2 = 0.5.
//
// Fully-coalesced variant: one thread per output float4-column pair.
// Each thread loads a float2 (2 adjacent input cols) from each band and
// writes one float4 into output row 2i and one into row 2i+1.
// Every warp-level load instr covers contiguous 256B; every store instr
// covers contiguous 512B (no half-covered 128B lines).

static constexpr int C2 = 64;                       // float2s per input row (w/2... = 128/2)
static constexpr int NROWS = 16 * 64 * 128;         // B*C*h = 131072
static constexpr int NTHREADS_TOTAL = NROWS * C2;   // 8,388,608

__global__ __launch_bounds__(256) void idwt_haar_kernel(
    const float2* __restrict__ LL,
    const float2* __restrict__ LH,
    const float2* __restrict__ HL,
    const float2* __restrict__ HH,
    float4* __restrict__ out)
{
    int tid = blockIdx.x * blockDim.x + threadIdx.x;
    if (tid >= NTHREADS_TOTAL) return;

    // input float2 index == tid  (row-major [NROWS, 64])
    float2 ll = __ldcs(&LL[tid]);
    float2 lh = __ldcs(&LH[tid]);
    float2 hl = __ldcs(&HL[tid]);
    float2 hh = __ldcs(&HH[tid]);

    int row = tid >> 6;        // bc*128 + i
    int c   = tid & 63;        // output float4 column index

    int bc = row >> 7;
    int i  = row & 127;

    // output [bc][256][256] f32 -> float4 row stride 64
    size_t obase = ((size_t)bc * 256 + 2 * i) * 64 + (size_t)c;

    float4 t, b;
    {
        float s0 = ll.x + hh.x, d0 = ll.x - hh.x;
        float s1 = lh.x + hl.x, d1 = lh.x - hl.x;
        t.x = 0.5f * (s0 - s1);
        t.y = 0.5f * (d0 + d1);
        b.x = 0.5f * (d0 - d1);
        b.y = 0.5f * (s0 + s1);
    }
    {
        float s0 = ll.y + hh.y, d0 = ll.y - hh.y;
        float s1 = lh.y + hl.y, d1 = lh.y - hl.y;
        t.z = 0.5f * (s0 - s1);
        t.w = 0.5f * (d0 + d1);
        b.z = 0.5f * (d0 - d1);
        b.w = 0.5f * (s0 + s1);
    }

    __stcs(&out[obase], t);
    __stcs(&out[obase + 64], b);
}

extern "C" void kernel_launch(void* const* d_in, const int* in_sizes, int n_in,
                              void* d_out, int out_size)
{
    const float2* LL = (const float2*)d_in[0];
    const float2* LH = (const float2*)d_in[1];
    const float2* HL = (const float2*)d_in[2];
    const float2* HH = (const float2*)d_in[3];

    float4* out = (float4*)d_out;

    int threads = 256;
    int blocks = NTHREADS_TOTAL / threads;  // 32768
    idwt_haar_kernel<<<blocks, threads>>>(LL, LH, HL, HH, out);
}